// round 6
// baseline (speedup 1.0000x reference)
#include <cuda_runtime.h>
#include <cstdint>

// Shapes (fixed by the problem)
#define BATCH   2
#define SEQ     4096
#define HEADS   16
#define DHEAD   64      // p
#define DSTATE  128     // n
#define LBLK    64      // block_len l

// Derivation: reference's decay_chunk row z=C (upper-triangular mask j>=i)
// keeps ONLY column j=C -> output depends on the LAST chunk alone:
//   out[b,h,p,n] = sum_l exp(2*S - cs[l]) * X[b,T-64+l,h,p] * B[b,T-64+l,h,n]
// with cs = inclusive cumsum of A over the last 64 steps, S = cs[63].
// Equivalently sum_l X_l (outer) (w_l * B_l) -- w folded into B.

__device__ __forceinline__ void cp_async16(uint32_t saddr, const void* gptr) {
    asm volatile("cp.async.cg.shared.global [%0], [%1], 16;"
                 :: "r"(saddr), "l"(gptr));
}

__global__ __launch_bounds__(512)
void chunk_state_last_kernel(const float* __restrict__ X,
                             const float* __restrict__ A,
                             const float* __restrict__ B,
                             float* __restrict__ out)
{
    const int bh = blockIdx.x;          // 0..31
    const int b  = bh >> 4;
    const int h  = bh & 15;
    const int n0 = blockIdx.y * 32;     // n-tile origin (4 tiles of 32)
    const int tid = threadIdx.x;        // 512 threads
    const int t0 = SEQ - LBLK;

    __shared__ __align__(16) float  Xs[LBLK][DHEAD];  // 16 KB [l][p]
    __shared__ __align__(16) float4 Bs[LBLK][8];      //  8 KB [l][n/4]
    __shared__ __align__(16) float  w[LBLK];

    // ---- 1) async-stage X and B tiles (independent of A; overlaps A scan) ----
    const float* Xbase = X + (((size_t)b * SEQ + t0) * HEADS + h) * DHEAD;
    const uint32_t xs_s = (uint32_t)__cvta_generic_to_shared(&Xs[0][0]);
    #pragma unroll
    for (int k = 0; k < 2; k++) {
        int i = tid + k * 512;          // 0..1023 float4 slots
        int l = i >> 4, c = i & 15;
        cp_async16(xs_s + i * 16, Xbase + (size_t)l * HEADS * DHEAD + c * 4);
    }
    const float* Bbase = B + (((size_t)b * SEQ + t0) * HEADS + h) * DSTATE + n0;
    const uint32_t bs_s = (uint32_t)__cvta_generic_to_shared(&Bs[0][0]);
    {
        int i = tid;                    // 0..511 float4 slots
        int l = i >> 3, c = i & 7;
        cp_async16(bs_s + i * 16, Bbase + (size_t)l * HEADS * DSTATE + c * 4);
    }
    asm volatile("cp.async.commit_group;");

    // ---- 2) warp 0 only: A scan (2 values/lane, pair-scan) + weights ----
    if (tid < 32) {
        const int lane = tid;
        const float* Abase = A + ((size_t)b * SEQ + t0) * HEADS + h;
        float a0 = Abase[(size_t)(2 * lane)     * HEADS];
        float a1 = Abase[(size_t)(2 * lane + 1) * HEADS];
        float v = a0 + a1;              // pair sum
        #pragma unroll
        for (int off = 1; off < 32; off <<= 1) {
            float up = __shfl_up_sync(0xFFFFFFFFu, v, off);
            if (lane >= off) v += up;
        }
        float S   = __shfl_sync(0xFFFFFFFFu, v, 31);  // total sum cs[63]
        float cs1 = v;                  // inclusive cumsum through 2*lane+1
        float cs0 = v - a1;             // inclusive cumsum through 2*lane
        w[2 * lane]     = __expf(2.f * S - cs0);
        w[2 * lane + 1] = __expf(2.f * S - cs1);
    }

    asm volatile("cp.async.wait_group 0;");
    __syncthreads();                    // tiles + w ready

    // ---- 3) premultiply w into Bs (one float4 per thread) ----
    {
        float4* p4 = (float4*)&Bs[0][0] + tid;
        float4 v = *p4;
        float wl = w[tid >> 3];
        v.x *= wl; v.y *= wl; v.z *= wl; v.w *= wl;
        *p4 = v;
    }
    __syncthreads();

    // ---- 4) rank-64 outer product; 1p x 4n per thread ----
    const int tn = tid & 7;             // n = n0 + tn*4 + j
    const int tp = tid >> 3;            // p = tp (0..63)
    float accx = 0.f, accy = 0.f, accz = 0.f, accw = 0.f;

    #pragma unroll 8
    for (int l = 0; l < LBLK; l++) {
        const float  xv = Xs[l][tp];
        const float4 bv = Bs[l][tn];    // w pre-applied
        accx += xv * bv.x; accy += xv * bv.y;
        accz += xv * bv.z; accw += xv * bv.w;
    }

    float* obase = out + ((size_t)(b * HEADS + h)) * DHEAD * DSTATE;
    *(float4*)(obase + (size_t)tp * DSTATE + n0 + tn * 4) =
        make_float4(accx, accy, accz, accw);
}

extern "C" void kernel_launch(void* const* d_in, const int* in_sizes, int n_in,
                              void* d_out, int out_size)
{
    const float* X = (const float*)d_in[0];   // (2,4096,16,64)  f32
    const float* A = (const float*)d_in[1];   // (2,4096,16)     f32
    const float* B = (const float*)d_in[2];   // (2,4096,16,128) f32
    float* out = (float*)d_out;               // (2,16,64,128)   f32

    dim3 grid(BATCH * HEADS, DSTATE / 32);    // 32 x 4 = 128 CTAs
    chunk_state_last_kernel<<<grid, 512>>>(X, A, B, out);
}

// round 8
// speedup vs baseline: 1.0664x; 1.0664x over previous
#include <cuda_runtime.h>
#include <cstdint>

// Shapes (fixed by the problem)
#define BATCH   2
#define SEQ     4096
#define HEADS   16
#define DHEAD   64      // p
#define DSTATE  128     // n
#define LBLK    64      // block_len l

// Derivation: reference's decay_chunk row z=C (upper-triangular mask j>=i)
// keeps ONLY column j=C -> output depends on the LAST chunk alone:
//   out[b,h,p,n] = sum_l exp(2*S - cs[l]) * X[b,T-64+l,h,p] * B[b,T-64+l,h,n]
// with cs = inclusive cumsum of A over the last 64 steps, S = cs[63].
// w folded into B:  out = sum_l X_l (outer) (w_l * B_l).

__device__ __forceinline__ void cp_async16(uint32_t saddr, const void* gptr) {
    asm volatile("cp.async.cg.shared.global [%0], [%1], 16;"
                 :: "r"(saddr), "l"(gptr));
}

__global__ __launch_bounds__(512)
void chunk_state_last_kernel(const float* __restrict__ X,
                             const float* __restrict__ A,
                             const float* __restrict__ B,
                             float* __restrict__ out)
{
    const int bh = blockIdx.x;          // 0..31
    const int b  = bh >> 4;
    const int h  = bh & 15;
    const int n0 = blockIdx.y * 32;     // n-tile origin (4 tiles of 32)
    const int tid = threadIdx.x;        // 512 threads
    const int t0 = SEQ - LBLK;

    __shared__ __align__(16) float  Xs[LBLK][DHEAD];  // 16 KB [l][p]; reused as reduction buf
    __shared__ __align__(16) float4 Bs[LBLK][8];      //  8 KB [l][n/4]
    __shared__ __align__(16) float  w[LBLK];

    // ---- 1) async-stage X and B tiles (independent of A; overlaps A scan) ----
    const float* Xbase = X + (((size_t)b * SEQ + t0) * HEADS + h) * DHEAD;
    const uint32_t xs_s = (uint32_t)__cvta_generic_to_shared(&Xs[0][0]);
    #pragma unroll
    for (int k = 0; k < 2; k++) {
        int i = tid + k * 512;          // 0..1023 float4 slots
        int l = i >> 4, c = i & 15;
        cp_async16(xs_s + i * 16, Xbase + (size_t)l * HEADS * DHEAD + c * 4);
    }
    const float* Bbase = B + (((size_t)b * SEQ + t0) * HEADS + h) * DSTATE + n0;
    const uint32_t bs_s = (uint32_t)__cvta_generic_to_shared(&Bs[0][0]);
    {
        int i = tid;                    // 0..511 float4 slots
        int l = i >> 3, c = i & 7;
        cp_async16(bs_s + i * 16, Bbase + (size_t)l * HEADS * DSTATE + c * 4);
    }
    asm volatile("cp.async.commit_group;");

    // ---- 2) warp 0 only: A scan (2 values/lane, pair-scan) + weights ----
    if (tid < 32) {
        const int lane = tid;
        const float* Abase = A + ((size_t)b * SEQ + t0) * HEADS + h;
        float a0 = Abase[(size_t)(2 * lane)     * HEADS];
        float a1 = Abase[(size_t)(2 * lane + 1) * HEADS];
        float v = a0 + a1;              // pair sum
        #pragma unroll
        for (int off = 1; off < 32; off <<= 1) {
            float up = __shfl_up_sync(0xFFFFFFFFu, v, off);
            if (lane >= off) v += up;
        }
        float S   = __shfl_sync(0xFFFFFFFFu, v, 31);  // total sum cs[63]
        float cs1 = v;                  // inclusive cumsum through 2*lane+1
        float cs0 = v - a1;             // inclusive cumsum through 2*lane
        w[2 * lane]     = __expf(2.f * S - cs0);
        w[2 * lane + 1] = __expf(2.f * S - cs1);
    }

    asm volatile("cp.async.wait_group 0;");
    __syncthreads();                    // tiles + w ready

    // ---- 3) premultiply w into Bs (one float4 per thread) ----
    {
        float4* p4 = (float4*)&Bs[0][0] + tid;
        float4 v = *p4;
        float wl = w[tid >> 3];
        v.x *= wl; v.y *= wl; v.z *= wl; v.w *= wl;
        *p4 = v;
    }
    __syncthreads();

    // ---- 4) split-l rank-32 outer product; 2p x 4n per thread ----
    const int half = tid >> 8;          // 0: l in [0,32), 1: l in [32,64)
    const int r    = tid & 255;
    const int tn   = r & 7;             // n = n0 + tn*4 + j
    const int tp   = r >> 3;            // p = tp*2 + {0,1}
    const int l0   = half * 32;

    float acc0x = 0.f, acc0y = 0.f, acc0z = 0.f, acc0w = 0.f;
    float acc1x = 0.f, acc1y = 0.f, acc1z = 0.f, acc1w = 0.f;

    #pragma unroll 8
    for (int li = 0; li < 32; li++) {
        const int l = l0 + li;
        const float2 xv = *(const float2*)&Xs[l][tp * 2];
        const float4 bv = Bs[l][tn];    // w pre-applied
        acc0x += xv.x * bv.x; acc0y += xv.x * bv.y;
        acc0z += xv.x * bv.z; acc0w += xv.x * bv.w;
        acc1x += xv.y * bv.x; acc1y += xv.y * bv.y;
        acc1z += xv.y * bv.z; acc1w += xv.y * bv.w;
    }

    // ---- 5) pairwise reduction (reuse Xs as 256 x 2 float4 buffer) ----
    __syncthreads();                    // all reads of Xs/Bs done
    float4* red = (float4*)&Xs[0][0];
    if (half == 1) {
        red[r * 2]     = make_float4(acc0x, acc0y, acc0z, acc0w);
        red[r * 2 + 1] = make_float4(acc1x, acc1y, acc1z, acc1w);
    }
    __syncthreads();
    if (half == 0) {
        const float4 p0 = red[r * 2];
        const float4 p1 = red[r * 2 + 1];
        float* obase = out + ((size_t)(b * HEADS + h)) * DHEAD * DSTATE;
        int p = tp * 2;
        *(float4*)(obase + (size_t)p * DSTATE + n0 + tn * 4) =
            make_float4(acc0x + p0.x, acc0y + p0.y, acc0z + p0.z, acc0w + p0.w);
        p = tp * 2 + 1;
        *(float4*)(obase + (size_t)p * DSTATE + n0 + tn * 4) =
            make_float4(acc1x + p1.x, acc1y + p1.y, acc1z + p1.z, acc1w + p1.w);
    }
}

extern "C" void kernel_launch(void* const* d_in, const int* in_sizes, int n_in,
                              void* d_out, int out_size)
{
    const float* X = (const float*)d_in[0];   // (2,4096,16,64)  f32
    const float* A = (const float*)d_in[1];   // (2,4096,16)     f32
    const float* B = (const float*)d_in[2];   // (2,4096,16,128) f32
    float* out = (float*)d_out;               // (2,16,64,128)   f32

    dim3 grid(BATCH * HEADS, DSTATE / 32);    // 32 x 4 = 128 CTAs
    chunk_state_last_kernel<<<grid, 512>>>(X, A, B, out);
}